// round 7
// baseline (speedup 1.0000x reference)
#include <cuda_runtime.h>
#include <cuda_bf16.h>
#include <math.h>
#include <stdint.h>

// Problem constants
#define BATCH   2
#define SEQ     2048
#define HID     2048
#define NHEADS  16
#define HDIM    128
#define MTOT    (BATCH * SEQ)        // 4096

// ---------------------------------------------------------------------------
// Scratch (__device__ globals; allocation-free rule)
// ---------------------------------------------------------------------------
__device__ __align__(16) __nv_bfloat16 g_hs_hi[MTOT * HID];
__device__ __align__(16) __nv_bfloat16 g_hs_lo[MTOT * HID];
__device__ __align__(16) __nv_bfloat16 g_ao_hi[MTOT * HID];
__device__ __align__(16) __nv_bfloat16 g_ao_lo[MTOT * HID];
__device__ __align__(16) __nv_bfloat16 g_w_hi[4][HID * HID];
__device__ __align__(16) __nv_bfloat16 g_w_lo[4][HID * HID];

__device__ __align__(16) __nv_bfloat16 g_qh[MTOT * HID];
__device__ __align__(16) __nv_bfloat16 g_ql[MTOT * HID];
__device__ __align__(16) __nv_bfloat16 g_kh[MTOT * HID];
__device__ __align__(16) __nv_bfloat16 g_kl[MTOT * HID];
__device__ __align__(16) __nv_bfloat16 g_vh[MTOT * HID];
__device__ __align__(16) __nv_bfloat16 g_vl[MTOT * HID];

__device__ __align__(16) float g_cosT[SEQ * 64];
__device__ __align__(16) float g_sinT[SEQ * 64];

// ---------------------------------------------------------------------------
// PTX helpers (baseline PTX only — compute_103 rejects tcgen05)
// ---------------------------------------------------------------------------
static __device__ __forceinline__ uint32_t smem_u32(const void* p) {
    uint32_t a;
    asm("{ .reg .u64 t; cvta.to.shared.u64 t, %1; cvt.u32.u64 %0, t; }"
        : "=r"(a) : "l"(p));
    return a;
}

#define CPA16(d, s)  asm volatile("cp.async.cg.shared.global [%0], [%1], 16;" :: "r"(d), "l"(s) : "memory")
#define CPA_COMMIT() asm volatile("cp.async.commit_group;" ::: "memory")
#define CPA_WAIT1()  asm volatile("cp.async.wait_group 1;" ::: "memory")
#define CPA_WAIT0()  asm volatile("cp.async.wait_group 0;" ::: "memory")

static __device__ __forceinline__ void ldsm4(uint32_t* r, uint32_t addr) {
    asm volatile("ldmatrix.sync.aligned.m8n8.x4.shared.b16 {%0,%1,%2,%3}, [%4];"
                 : "=r"(r[0]), "=r"(r[1]), "=r"(r[2]), "=r"(r[3]) : "r"(addr));
}
static __device__ __forceinline__ void ldsm4t(uint32_t* r, uint32_t addr) {
    asm volatile("ldmatrix.sync.aligned.m8n8.x4.trans.shared.b16 {%0,%1,%2,%3}, [%4];"
                 : "=r"(r[0]), "=r"(r[1]), "=r"(r[2]), "=r"(r[3]) : "r"(addr));
}
static __device__ __forceinline__ void mma16816(float* d, const uint32_t* a, const uint32_t* b) {
    asm volatile("mma.sync.aligned.m16n8k16.row.col.f32.bf16.bf16.f32 "
                 "{%0,%1,%2,%3}, {%4,%5,%6,%7}, {%8,%9}, {%0,%1,%2,%3};"
                 : "+f"(d[0]), "+f"(d[1]), "+f"(d[2]), "+f"(d[3])
                 : "r"(a[0]), "r"(a[1]), "r"(a[2]), "r"(a[3]), "r"(b[0]), "r"(b[1]));
}

static __device__ __forceinline__ uint32_t pack_bf2(float a, float b) {
    __nv_bfloat162 t = __floats2bfloat162_rn(a, b);
    return *reinterpret_cast<uint32_t*>(&t);
}

// ---------------------------------------------------------------------------
// Split fp32 -> (hi, lo) bf16
// ---------------------------------------------------------------------------
__global__ __launch_bounds__(256) void split_kernel(const float* __restrict__ x,
                                                    __nv_bfloat16* __restrict__ hi,
                                                    __nv_bfloat16* __restrict__ lo,
                                                    int n4) {
    int i = blockIdx.x * 256 + threadIdx.x;
    if (i >= n4) return;
    float4 f = ((const float4*)x)[i];
    float v[4] = {f.x, f.y, f.z, f.w};
    __align__(8) __nv_bfloat16 h[4], l[4];
#pragma unroll
    for (int j = 0; j < 4; j++) {
        h[j] = __float2bfloat16_rn(v[j]);
        l[j] = __float2bfloat16_rn(v[j] - __bfloat162float(h[j]));
    }
    *reinterpret_cast<uint2*>(hi + (size_t)4 * i) = *reinterpret_cast<uint2*>(h);
    *reinterpret_cast<uint2*>(lo + (size_t)4 * i) = *reinterpret_cast<uint2*>(l);
}

__global__ __launch_bounds__(256) void split_w4(
    const float* __restrict__ w0, const float* __restrict__ w1,
    const float* __restrict__ w2, const float* __restrict__ w3,
    __nv_bfloat16* __restrict__ hi, __nv_bfloat16* __restrict__ lo, int n4) {
    int i = blockIdx.x * 256 + threadIdx.x;
    if (i >= n4) return;
    int w = blockIdx.y;
    const float* x = (w == 0) ? w0 : (w == 1) ? w1 : (w == 2) ? w2 : w3;
    size_t off = (size_t)w * (size_t)HID * HID;
    float4 f = ((const float4*)x)[i];
    float v[4] = {f.x, f.y, f.z, f.w};
    __align__(8) __nv_bfloat16 h[4], l[4];
#pragma unroll
    for (int j = 0; j < 4; j++) {
        h[j] = __float2bfloat16_rn(v[j]);
        l[j] = __float2bfloat16_rn(v[j] - __bfloat162float(h[j]));
    }
    *reinterpret_cast<uint2*>(hi + off + (size_t)4 * i) = *reinterpret_cast<uint2*>(h);
    *reinterpret_cast<uint2*>(lo + off + (size_t)4 * i) = *reinterpret_cast<uint2*>(l);
}

// ---------------------------------------------------------------------------
// RoPE table (fp64-accurate phases)
// ---------------------------------------------------------------------------
__global__ __launch_bounds__(256) void rope_table(float* __restrict__ cosT,
                                                  float* __restrict__ sinT) {
    int idx = blockIdx.x * 256 + threadIdx.x;
    int i = idx & 63;
    int s = idx >> 6;
    double inv = pow(10000.0, -(double)i / 64.0);
    double sp, cp;
    sincos((double)s * inv, &sp, &cp);
    cosT[idx] = (float)cp;
    sinT[idx] = (float)sp;
}

// ---------------------------------------------------------------------------
// Split-bf16 GEMM on mma.sync: C = A * B^T (K-major), 128x128 tile, BK=32,
// 512 threads, 3-stage cp.async pipeline (one barrier per K-iter).
// Inner loop: load ALL fragments for a k16 step, then issue 24 MMAs
// term-major (8 independent accumulators between dependent writes).
// EPI 0: fp32 store (O-proj).  EPI 2: z=0/1 -> RoPE+split (Q/K), z=2 -> split (V).
// ---------------------------------------------------------------------------
#define BK      32
#define ASTRIDE 80
#define TILEB   (128 * ASTRIDE)
#define OFF_AHI 0
#define OFF_ALO (1 * TILEB)
#define OFF_BHI (2 * TILEB)
#define OFF_BLO (3 * TILEB)
#define STAGEB  (4 * TILEB)           // 40960
#define GSMEM   (3 * STAGEB)          // 122880 (1 CTA/SM)

template <int EPI>
__global__ __launch_bounds__(512) void gemm_mma(
    const __nv_bfloat16* __restrict__ Ahi, const __nv_bfloat16* __restrict__ Alo,
    const __nv_bfloat16* __restrict__ Bhi0, const __nv_bfloat16* __restrict__ Blo0,
    const __nv_bfloat16* __restrict__ Bhi1, const __nv_bfloat16* __restrict__ Blo1,
    const __nv_bfloat16* __restrict__ Bhi2, const __nv_bfloat16* __restrict__ Blo2,
    float* __restrict__ C,
    __nv_bfloat16* __restrict__ Hi0, __nv_bfloat16* __restrict__ Lo0,
    __nv_bfloat16* __restrict__ Hi1, __nv_bfloat16* __restrict__ Lo1,
    __nv_bfloat16* __restrict__ Hi2, __nv_bfloat16* __restrict__ Lo2,
    const float* __restrict__ cosT, const float* __restrict__ sinT) {
    extern __shared__ char smem[];
    const uint32_t sb = smem_u32(smem);
    const int tid = threadIdx.x;
    const int m0 = blockIdx.y * 128, n0 = blockIdx.x * 128;
    const int lane = tid & 31, wid = tid >> 5;
    const int wm = wid >> 2, wn = wid & 3;
    const int z = (EPI == 2) ? blockIdx.z : 0;

    const __nv_bfloat16* Bhi = (z == 0) ? Bhi0 : (z == 1) ? Bhi1 : Bhi2;
    const __nv_bfloat16* Blo = (z == 0) ? Blo0 : (z == 1) ? Blo1 : Blo2;

    const int lrow = tid >> 2;
    const int lc16 = tid & 3;
    const uint32_t sofs = lrow * ASTRIDE + lc16 * 16;

    const __nv_bfloat16* a_hi_base = Ahi + (size_t)(m0 + lrow) * HID + lc16 * 8;
    const __nv_bfloat16* a_lo_base = Alo + (size_t)(m0 + lrow) * HID + lc16 * 8;
    const __nv_bfloat16* b_hi_base = Bhi + (size_t)(n0 + lrow) * HID + lc16 * 8;
    const __nv_bfloat16* b_lo_base = Blo + (size_t)(n0 + lrow) * HID + lc16 * 8;

    float acc[2][4][4];
#pragma unroll
    for (int t = 0; t < 2; t++)
#pragma unroll
        for (int nt = 0; nt < 4; nt++)
#pragma unroll
            for (int e = 0; e < 4; e++) acc[t][nt][e] = 0.f;

    const uint32_t a_ld = sb + (uint32_t)((wm * 32 + (lane & 15)) * ASTRIDE + (lane >> 4) * 16);
    const uint32_t b_ld = sb + (uint32_t)((wn * 32 + ((lane >> 4) & 1) * 8 + (lane & 7)) * ASTRIDE
                                          + ((lane >> 3) & 1) * 16);

    const int NKT = HID / BK;   // 64

    // Prologue: stages 0, 1
#pragma unroll
    for (int p = 0; p < 2; p++) {
        uint32_t d = sb + p * STAGEB + sofs;
        size_t ge = (size_t)p * BK;
        CPA16(d + OFF_AHI, a_hi_base + ge);
        CPA16(d + OFF_ALO, a_lo_base + ge);
        CPA16(d + OFF_BHI, b_hi_base + ge);
        CPA16(d + OFF_BLO, b_lo_base + ge);
        CPA_COMMIT();
    }

    uint32_t st = 0, ld = 2 * STAGEB;
    for (int kt = 0; kt < NKT; kt++) {
        CPA_WAIT1();
        __syncthreads();   // stage st ready; all warps finished computing slot ld

        if (kt + 2 < NKT) {
            uint32_t d = sb + ld + sofs;
            size_t ge = (size_t)(kt + 2) * BK;
            CPA16(d + OFF_AHI, a_hi_base + ge);
            CPA16(d + OFF_ALO, a_lo_base + ge);
            CPA16(d + OFF_BHI, b_hi_base + ge);
            CPA16(d + OFF_BLO, b_lo_base + ge);
        }
        CPA_COMMIT();

#pragma unroll
        for (int ksub = 0; ksub < 2; ksub++) {
            const uint32_t ko = ksub * 32;
            // Load ALL fragments for this k16 step (breaks ldsm->mma chaining)
            uint32_t ah[2][4], al[2][4], bh[2][4], bl[2][4];
#pragma unroll
            for (int t = 0; t < 2; t++) {
                ldsm4(ah[t], a_ld + st + OFF_AHI + t * (16 * ASTRIDE) + ko);
                ldsm4(al[t], a_ld + st + OFF_ALO + t * (16 * ASTRIDE) + ko);
            }
#pragma unroll
            for (int p = 0; p < 2; p++) {
                ldsm4(bh[p], b_ld + st + OFF_BHI + p * (16 * ASTRIDE) + ko);
                ldsm4(bl[p], b_ld + st + OFF_BLO + p * (16 * ASTRIDE) + ko);
            }
            // Term-major issue: 8 independent accumulators between dependent MMAs
#pragma unroll
            for (int t = 0; t < 2; t++)
#pragma unroll
                for (int p = 0; p < 2; p++)
#pragma unroll
                    for (int hf = 0; hf < 2; hf++)
                        mma16816(acc[t][p * 2 + hf], ah[t], &bh[p][hf * 2]);
#pragma unroll
            for (int t = 0; t < 2; t++)
#pragma unroll
                for (int p = 0; p < 2; p++)
#pragma unroll
                    for (int hf = 0; hf < 2; hf++)
                        mma16816(acc[t][p * 2 + hf], al[t], &bh[p][hf * 2]);
#pragma unroll
            for (int t = 0; t < 2; t++)
#pragma unroll
                for (int p = 0; p < 2; p++)
#pragma unroll
                    for (int hf = 0; hf < 2; hf++)
                        mma16816(acc[t][p * 2 + hf], ah[t], &bl[p][hf * 2]);
        }
        st += STAGEB; if (st == 3 * STAGEB) st = 0;
        ld += STAGEB; if (ld == 3 * STAGEB) ld = 0;
    }

    if (EPI == 0) {
#pragma unroll
        for (int t = 0; t < 2; t++) {
            int row = m0 + wm * 32 + t * 16 + (lane >> 2);
#pragma unroll
            for (int nt = 0; nt < 4; nt++) {
                int col = n0 + wn * 32 + nt * 8 + (lane & 3) * 2;
                *(float2*)&C[(size_t)row * HID + col] =
                    make_float2(acc[t][nt][0], acc[t][nt][1]);
                *(float2*)&C[(size_t)(row + 8) * HID + col] =
                    make_float2(acc[t][nt][2], acc[t][nt][3]);
            }
        }
    } else if (z == 2) {
        // V projection: split hi/lo store from registers
#pragma unroll
        for (int t = 0; t < 2; t++) {
            int row = m0 + wm * 32 + t * 16 + (lane >> 2);
#pragma unroll
            for (int nt = 0; nt < 4; nt++) {
                int col = n0 + wn * 32 + nt * 8 + (lane & 3) * 2;
#pragma unroll
                for (int half = 0; half < 2; half++) {
                    float v0 = acc[t][nt][half * 2], v1 = acc[t][nt][half * 2 + 1];
                    __nv_bfloat162 hh = __floats2bfloat162_rn(v0, v1);
                    uint32_t hu = *reinterpret_cast<uint32_t*>(&hh);
                    uint32_t lu = pack_bf2(v0 - __low2float(hh), v1 - __high2float(hh));
                    size_t o = (size_t)(row + half * 8) * HID + col;
                    *(uint32_t*)&Hi2[o] = hu;
                    *(uint32_t*)&Lo2[o] = lu;
                }
            }
        }
    } else {
        // Q/K projection: RoPE + split via smem staging
        __nv_bfloat16* Hi = z ? Hi1 : Hi0;
        __nv_bfloat16* Lo = z ? Lo1 : Lo0;
        float* smf = (float*)smem;     // [128][132] fp32
        CPA_WAIT0();
        __syncthreads();
#pragma unroll
        for (int t = 0; t < 2; t++) {
            int r = wm * 32 + t * 16 + (lane >> 2);
            int c = wn * 32 + (lane & 3) * 2;
#pragma unroll
            for (int nt = 0; nt < 4; nt++) {
                int cc = c + nt * 8;
                smf[r * 132 + cc]       = acc[t][nt][0];
                smf[r * 132 + cc + 1]   = acc[t][nt][1];
                smf[(r + 8) * 132 + cc]     = acc[t][nt][2];
                smf[(r + 8) * 132 + cc + 1] = acc[t][nt][3];
            }
        }
        __syncthreads();
#pragma unroll
        for (int it = 0; it < 8; it++) {
            int p = it * 512 + tid;
            int row = p >> 5;
            int i2 = (p & 31) * 2;
            float2 x1 = *(float2*)&smf[row * 132 + i2];
            float2 x2 = *(float2*)&smf[row * 132 + 64 + i2];
            int grow = m0 + row;
            int s = grow & (SEQ - 1);
            float2 cs = *(const float2*)&cosT[s * 64 + i2];
            float2 sn = *(const float2*)&sinT[s * 64 + i2];
            float r1a = x1.x * cs.x - x2.x * sn.x;
            float r1b = x1.y * cs.y - x2.y * sn.y;
            float r2a = x2.x * cs.x + x1.x * sn.x;
            float r2b = x2.y * cs.y + x1.y * sn.y;
            __nv_bfloat162 h1 = __floats2bfloat162_rn(r1a, r1b);
            __nv_bfloat162 h2 = __floats2bfloat162_rn(r2a, r2b);
            uint32_t l1 = pack_bf2(r1a - __low2float(h1), r1b - __high2float(h1));
            uint32_t l2 = pack_bf2(r2a - __low2float(h2), r2b - __high2float(h2));
            size_t o1 = (size_t)grow * HID + n0 + i2;
            *(uint32_t*)&Hi[o1]      = *reinterpret_cast<uint32_t*>(&h1);
            *(uint32_t*)&Hi[o1 + 64] = *reinterpret_cast<uint32_t*>(&h2);
            *(uint32_t*)&Lo[o1]      = l1;
            *(uint32_t*)&Lo[o1 + 64] = l2;
        }
    }
}

// ---------------------------------------------------------------------------
// Tensor-core flash attention (split-bf16, causal) — unchanged
// ---------------------------------------------------------------------------
#define AST    272
#define ATILE  (64 * AST)
#define A_QH   0
#define A_QL   (1 * ATILE)
#define A_KH   (2 * ATILE)
#define A_KL   (3 * ATILE)
#define A_VH   (4 * ATILE)
#define A_VL   (5 * ATILE)
#define ASMEM  (6 * ATILE)

__global__ __launch_bounds__(128) void attn_tc(
    const __nv_bfloat16* __restrict__ qh, const __nv_bfloat16* __restrict__ ql,
    const __nv_bfloat16* __restrict__ kh, const __nv_bfloat16* __restrict__ kl,
    const __nv_bfloat16* __restrict__ vh, const __nv_bfloat16* __restrict__ vl,
    __nv_bfloat16* __restrict__ aoh, __nv_bfloat16* __restrict__ aol) {
    extern __shared__ char smc[];
    const uint32_t sb = smem_u32(smc);
    const int tid = threadIdx.x, lane = tid & 31, wid = tid >> 5;
    const int qt = gridDim.x - 1 - blockIdx.x;
    const int bh = blockIdx.y;
    const int b = bh >> 4, h = bh & 15;
    const size_t hoff = (size_t)b * SEQ * HID + (size_t)h * HDIM;

    {
        const size_t qbase = hoff + (size_t)(qt * 64) * HID;
#pragma unroll
        for (int i = 0; i < 8; i++) {
            int idx = i * 128 + tid, row = idx >> 4, c16 = idx & 15;
            uint32_t so = row * AST + c16 * 16;
            size_t go = qbase + (size_t)row * HID + c16 * 8;
            CPA16(sb + A_QH + so, qh + go);
            CPA16(sb + A_QL + so, ql + go);
        }
        CPA_COMMIT();
    }

    float o[16][4];
#pragma unroll
    for (int nt = 0; nt < 16; nt++)
#pragma unroll
        for (int e = 0; e < 4; e++) o[nt][e] = 0.f;
    float m0 = -1e30f, m1 = -1e30f, l0 = 0.f, l1 = 0.f;
    const float scale = 0.08838834764831845f;

    const uint32_t a_q = sb + (uint32_t)((wid * 16 + (lane & 15)) * AST + (lane >> 4) * 16);
    const uint32_t b_k = sb + (uint32_t)((((lane & 7) + ((lane >> 4) & 1) * 8)) * AST + ((lane >> 3) & 1) * 16);
    const uint32_t b_v = sb + (uint32_t)((((lane & 7) + ((lane >> 3) & 1) * 8)) * AST + ((lane >> 4) & 1) * 16);

    const int grow0 = qt * 64 + wid * 16 + (lane >> 2);

    for (int j = 0; j <= qt; j++) {
        __syncthreads();
        {
            const size_t kbase = hoff + (size_t)(j * 64) * HID;
#pragma unroll
            for (int i = 0; i < 8; i++) {
                int idx = i * 128 + tid, row = idx >> 4, c16 = idx & 15;
                uint32_t so = row * AST + c16 * 16;
                size_t go = kbase + (size_t)row * HID + c16 * 8;
                CPA16(sb + A_KH + so, kh + go);
                CPA16(sb + A_KL + so, kl + go);
                CPA16(sb + A_VH + so, vh + go);
                CPA16(sb + A_VL + so, vl + go);
            }
            CPA_COMMIT();
        }
        CPA_WAIT0();
        __syncthreads();

        float s[8][4];
#pragma unroll
        for (int nt = 0; nt < 8; nt++)
#pragma unroll
            for (int e = 0; e < 4; e++) s[nt][e] = 0.f;

#pragma unroll
        for (int ks = 0; ks < 8; ks++) {
            uint32_t aH[4], aL[4];
            ldsm4(aH, a_q + A_QH + ks * 32);
            ldsm4(aL, a_q + A_QL + ks * 32);
#pragma unroll
            for (int g = 0; g < 4; g++) {
                uint32_t bH[4], bL[4];
                ldsm4(bH, b_k + A_KH + g * (16 * AST) + ks * 32);
                ldsm4(bL, b_k + A_KL + g * (16 * AST) + ks * 32);
                mma16816(s[2 * g],     aH, bH);     mma16816(s[2 * g + 1], aH, bH + 2);
                mma16816(s[2 * g],     aL, bH);     mma16816(s[2 * g + 1], aL, bH + 2);
                mma16816(s[2 * g],     aH, bL);     mma16816(s[2 * g + 1], aH, bL + 2);
            }
        }

        const bool diag = (j == qt);
        float mx0 = -1e30f, mx1 = -1e30f;
#pragma unroll
        for (int nt = 0; nt < 8; nt++) {
            int c0 = j * 64 + nt * 8 + (lane & 3) * 2;
#pragma unroll
            for (int e = 0; e < 4; e++) {
                float v = s[nt][e] * scale;
                if (diag && (c0 + (e & 1)) > (grow0 + (e >> 1) * 8)) v = -1e30f;
                s[nt][e] = v;
            }
            mx0 = fmaxf(mx0, fmaxf(s[nt][0], s[nt][1]));
            mx1 = fmaxf(mx1, fmaxf(s[nt][2], s[nt][3]));
        }
        mx0 = fmaxf(mx0, __shfl_xor_sync(0xffffffffu, mx0, 1));
        mx0 = fmaxf(mx0, __shfl_xor_sync(0xffffffffu, mx0, 2));
        mx1 = fmaxf(mx1, __shfl_xor_sync(0xffffffffu, mx1, 1));
        mx1 = fmaxf(mx1, __shfl_xor_sync(0xffffffffu, mx1, 2));
        float mn0 = fmaxf(m0, mx0), mn1 = fmaxf(m1, mx1);
        float cr0 = __expf(m0 - mn0), cr1 = __expf(m1 - mn1);
        m0 = mn0; m1 = mn1;
        float sum0 = 0.f, sum1 = 0.f;
#pragma unroll
        for (int nt = 0; nt < 8; nt++) {
            s[nt][0] = __expf(s[nt][0] - mn0);
            s[nt][1] = __expf(s[nt][1] - mn0);
            s[nt][2] = __expf(s[nt][2] - mn1);
            s[nt][3] = __expf(s[nt][3] - mn1);
            sum0 += s[nt][0] + s[nt][1];
            sum1 += s[nt][2] + s[nt][3];
        }
        sum0 += __shfl_xor_sync(0xffffffffu, sum0, 1);
        sum0 += __shfl_xor_sync(0xffffffffu, sum0, 2);
        sum1 += __shfl_xor_sync(0xffffffffu, sum1, 1);
        sum1 += __shfl_xor_sync(0xffffffffu, sum1, 2);
        l0 = l0 * cr0 + sum0;
        l1 = l1 * cr1 + sum1;
#pragma unroll
        for (int nt = 0; nt < 16; nt++) {
            o[nt][0] *= cr0; o[nt][1] *= cr0;
            o[nt][2] *= cr1; o[nt][3] *= cr1;
        }

#pragma unroll
        for (int kc = 0; kc < 4; kc++) {
            float p00 = s[2 * kc][0], p01 = s[2 * kc][1], p02 = s[2 * kc][2], p03 = s[2 * kc][3];
            float p10 = s[2 * kc + 1][0], p11 = s[2 * kc + 1][1], p12 = s[2 * kc + 1][2], p13 = s[2 * kc + 1][3];
            uint32_t pH[4], pL[4];
            __nv_bfloat162 t;
            t = __floats2bfloat162_rn(p00, p01); pH[0] = *reinterpret_cast<uint32_t*>(&t);
            pL[0] = pack_bf2(p00 - __low2float(t), p01 - __high2float(t));
            t = __floats2bfloat162_rn(p02, p03); pH[1] = *reinterpret_cast<uint32_t*>(&t);
            pL[1] = pack_bf2(p02 - __low2float(t), p03 - __high2float(t));
            t = __floats2bfloat162_rn(p10, p11); pH[2] = *reinterpret_cast<uint32_t*>(&t);
            pL[2] = pack_bf2(p10 - __low2float(t), p11 - __high2float(t));
            t = __floats2bfloat162_rn(p12, p13); pH[3] = *reinterpret_cast<uint32_t*>(&t);
            pL[3] = pack_bf2(p12 - __low2float(t), p13 - __high2float(t));

            uint32_t vbase = b_v + kc * (16 * AST);
#pragma unroll
            for (int ng = 0; ng < 8; ng++) {
                uint32_t vH[4], vL[4];
                ldsm4t(vH, vbase + A_VH + ng * 32);
                ldsm4t(vL, vbase + A_VL + ng * 32);
                mma16816(o[2 * ng],     pH, vH);     mma16816(o[2 * ng + 1], pH, vH + 2);
                mma16816(o[2 * ng],     pL, vH);     mma16816(o[2 * ng + 1], pL, vH + 2);
                mma16816(o[2 * ng],     pH, vL);     mma16816(o[2 * ng + 1], pH, vL + 2);
            }
        }
    }

    float inv0 = 1.f / l0, inv1 = 1.f / l1;
    int row0 = b * SEQ + qt * 64 + wid * 16 + (lane >> 2);
#pragma unroll
    for (int nt = 0; nt < 16; nt++) {
        int col = h * HDIM + nt * 8 + (lane & 3) * 2;
        float v0 = o[nt][0] * inv0, v1 = o[nt][1] * inv0;
        float v2 = o[nt][2] * inv1, v3 = o[nt][3] * inv1;
        __nv_bfloat162 t0 = __floats2bfloat162_rn(v0, v1);
        __nv_bfloat162 t1 = __floats2bfloat162_rn(v2, v3);
        uint32_t h0 = *reinterpret_cast<uint32_t*>(&t0);
        uint32_t h1 = *reinterpret_cast<uint32_t*>(&t1);
        uint32_t lo0 = pack_bf2(v0 - __low2float(t0), v1 - __high2float(t0));
        uint32_t lo1 = pack_bf2(v2 - __low2float(t1), v3 - __high2float(t1));
        *(uint32_t*)&aoh[(size_t)row0 * HID + col]       = h0;
        *(uint32_t*)&aoh[(size_t)(row0 + 8) * HID + col] = h1;
        *(uint32_t*)&aol[(size_t)row0 * HID + col]       = lo0;
        *(uint32_t*)&aol[(size_t)(row0 + 8) * HID + col] = lo1;
    }
}

// ---------------------------------------------------------------------------
// Launch
// ---------------------------------------------------------------------------
extern "C" void kernel_launch(void* const* d_in, const int* in_sizes, int n_in,
                              void* d_out, int out_size) {
    const float* hs = (const float*)d_in[0];
    const float* Wq = (const float*)d_in[1];
    const float* Wk = (const float*)d_in[2];
    const float* Wv = (const float*)d_in[3];
    const float* Wo = (const float*)d_in[4];
    float* out = (float*)d_out;

    float *cosT, *sinT;
    cudaGetSymbolAddress((void**)&cosT, g_cosT);
    cudaGetSymbolAddress((void**)&sinT, g_sinT);

    __nv_bfloat16 *hs_hi, *hs_lo, *ao_hi, *ao_lo, *w_hi, *w_lo;
    __nv_bfloat16 *qhp, *qlp, *khp, *klp, *vhp, *vlp;
    cudaGetSymbolAddress((void**)&hs_hi, g_hs_hi);
    cudaGetSymbolAddress((void**)&hs_lo, g_hs_lo);
    cudaGetSymbolAddress((void**)&ao_hi, g_ao_hi);
    cudaGetSymbolAddress((void**)&ao_lo, g_ao_lo);
    cudaGetSymbolAddress((void**)&w_hi,  g_w_hi);
    cudaGetSymbolAddress((void**)&w_lo,  g_w_lo);
    cudaGetSymbolAddress((void**)&qhp, g_qh);
    cudaGetSymbolAddress((void**)&qlp, g_ql);
    cudaGetSymbolAddress((void**)&khp, g_kh);
    cudaGetSymbolAddress((void**)&klp, g_kl);
    cudaGetSymbolAddress((void**)&vhp, g_vh);
    cudaGetSymbolAddress((void**)&vlp, g_vl);

    const size_t WN = (size_t)HID * HID;
    const int n4_hs = MTOT * HID / 4;
    const int n4_w  = (int)(WN / 4);

    split_kernel<<<(n4_hs + 255) / 256, 256>>>(hs, hs_hi, hs_lo, n4_hs);
    split_w4<<<dim3((n4_w + 255) / 256, 4), 256>>>(Wq, Wk, Wv, Wo, w_hi, w_lo, n4_w);
    rope_table<<<(SEQ * 64) / 256, 256>>>(cosT, sinT);

    cudaFuncSetAttribute(gemm_mma<0>, cudaFuncAttributeMaxDynamicSharedMemorySize, GSMEM);
    cudaFuncSetAttribute(gemm_mma<2>, cudaFuncAttributeMaxDynamicSharedMemorySize, GSMEM);

    dim3 gg(HID / 128, MTOT / 128);          // (16, 32)
    dim3 gg3(HID / 128, MTOT / 128, 3);      // Q, K, V in one launch

    gemm_mma<2><<<gg3, 512, GSMEM>>>(hs_hi, hs_lo,
                                     w_hi + 0 * WN, w_lo + 0 * WN,
                                     w_hi + 1 * WN, w_lo + 1 * WN,
                                     w_hi + 2 * WN, w_lo + 2 * WN,
                                     nullptr,
                                     qhp, qlp, khp, klp, vhp, vlp, cosT, sinT);

    cudaFuncSetAttribute(attn_tc, cudaFuncAttributeMaxDynamicSharedMemorySize, ASMEM);
    attn_tc<<<dim3(SEQ / 64, BATCH * NHEADS), 128, ASMEM>>>(qhp, qlp, khp, klp, vhp, vlp, ao_hi, ao_lo);

    gemm_mma<0><<<gg, 512, GSMEM>>>(ao_hi, ao_lo,
                                    w_hi + 3 * WN, w_lo + 3 * WN,
                                    nullptr, nullptr, nullptr, nullptr,
                                    out,
                                    nullptr, nullptr, nullptr, nullptr, nullptr, nullptr,
                                    nullptr, nullptr);
}

// round 8
// speedup vs baseline: 4.0433x; 4.0433x over previous
#include <cuda_runtime.h>
#include <cuda_fp16.h>
#include <math.h>
#include <stdint.h>

// Problem constants
#define BATCH   2
#define SEQ     2048
#define HID     2048
#define NHEADS  16
#define HDIM    128
#define MTOT    (BATCH * SEQ)        // 4096

// ---------------------------------------------------------------------------
// Scratch (__device__ globals; allocation-free rule)  — single fp16 buffers
// ---------------------------------------------------------------------------
__device__ __align__(16) __half g_hs[MTOT * HID];
__device__ __align__(16) __half g_ao[MTOT * HID];
__device__ __align__(16) __half g_w[4][HID * HID];
__device__ __align__(16) __half g_q[MTOT * HID];
__device__ __align__(16) __half g_k[MTOT * HID];
__device__ __align__(16) __half g_v[MTOT * HID];

__device__ __align__(16) float g_cosT[SEQ * 64];
__device__ __align__(16) float g_sinT[SEQ * 64];

// ---------------------------------------------------------------------------
// PTX helpers (baseline PTX only — compute_103 rejects tcgen05)
// ---------------------------------------------------------------------------
static __device__ __forceinline__ uint32_t smem_u32(const void* p) {
    uint32_t a;
    asm("{ .reg .u64 t; cvta.to.shared.u64 t, %1; cvt.u32.u64 %0, t; }"
        : "=r"(a) : "l"(p));
    return a;
}

#define CPA16(d, s)  asm volatile("cp.async.cg.shared.global [%0], [%1], 16;" :: "r"(d), "l"(s) : "memory")
#define CPA_COMMIT() asm volatile("cp.async.commit_group;" ::: "memory")
#define CPA_WAIT1()  asm volatile("cp.async.wait_group 1;" ::: "memory")
#define CPA_WAIT0()  asm volatile("cp.async.wait_group 0;" ::: "memory")

static __device__ __forceinline__ void ldsm4(uint32_t* r, uint32_t addr) {
    asm volatile("ldmatrix.sync.aligned.m8n8.x4.shared.b16 {%0,%1,%2,%3}, [%4];"
                 : "=r"(r[0]), "=r"(r[1]), "=r"(r[2]), "=r"(r[3]) : "r"(addr));
}
static __device__ __forceinline__ void ldsm4t(uint32_t* r, uint32_t addr) {
    asm volatile("ldmatrix.sync.aligned.m8n8.x4.trans.shared.b16 {%0,%1,%2,%3}, [%4];"
                 : "=r"(r[0]), "=r"(r[1]), "=r"(r[2]), "=r"(r[3]) : "r"(addr));
}
// fp16 MMA, fp32 accumulate
static __device__ __forceinline__ void mma_f16(float* d, const uint32_t* a, const uint32_t* b) {
    asm volatile("mma.sync.aligned.m16n8k16.row.col.f32.f16.f16.f32 "
                 "{%0,%1,%2,%3}, {%4,%5,%6,%7}, {%8,%9}, {%0,%1,%2,%3};"
                 : "+f"(d[0]), "+f"(d[1]), "+f"(d[2]), "+f"(d[3])
                 : "r"(a[0]), "r"(a[1]), "r"(a[2]), "r"(a[3]), "r"(b[0]), "r"(b[1]));
}

static __device__ __forceinline__ uint32_t pack_h2(float a, float b) {
    __half2 t = __floats2half2_rn(a, b);
    return *reinterpret_cast<uint32_t*>(&t);
}

// ---------------------------------------------------------------------------
// Convert fp32 -> fp16
// ---------------------------------------------------------------------------
__global__ __launch_bounds__(256) void cvt_kernel(const float* __restrict__ x,
                                                  __half* __restrict__ y, int n4) {
    int i = blockIdx.x * 256 + threadIdx.x;
    if (i >= n4) return;
    float4 f = ((const float4*)x)[i];
    uint2 o;
    o.x = pack_h2(f.x, f.y);
    o.y = pack_h2(f.z, f.w);
    *reinterpret_cast<uint2*>(y + (size_t)4 * i) = o;
}

__global__ __launch_bounds__(256) void cvt_w4(
    const float* __restrict__ w0, const float* __restrict__ w1,
    const float* __restrict__ w2, const float* __restrict__ w3,
    __half* __restrict__ y, int n4) {
    int i = blockIdx.x * 256 + threadIdx.x;
    if (i >= n4) return;
    int w = blockIdx.y;
    const float* x = (w == 0) ? w0 : (w == 1) ? w1 : (w == 2) ? w2 : w3;
    size_t off = (size_t)w * (size_t)HID * HID;
    float4 f = ((const float4*)x)[i];
    uint2 o;
    o.x = pack_h2(f.x, f.y);
    o.y = pack_h2(f.z, f.w);
    *reinterpret_cast<uint2*>(y + off + (size_t)4 * i) = o;
}

// ---------------------------------------------------------------------------
// RoPE table (fp64-accurate phases)
// ---------------------------------------------------------------------------
__global__ __launch_bounds__(256) void rope_table(float* __restrict__ cosT,
                                                  float* __restrict__ sinT) {
    int idx = blockIdx.x * 256 + threadIdx.x;
    int i = idx & 63;
    int s = idx >> 6;
    double inv = pow(10000.0, -(double)i / 64.0);
    double sp, cp;
    sincos((double)s * inv, &sp, &cp);
    cosT[idx] = (float)cp;
    sinT[idx] = (float)sp;
}

// ---------------------------------------------------------------------------
// fp16 GEMM on mma.sync: C = A * B^T (K-major), 128x128 tile, BK=32,
// 512 threads, 3-stage cp.async pipeline, 2 CTAs/SM.
// Inner loop uses the R6-validated interleaved order.
// EPI 0: fp32 store (O-proj).  EPI 2: z=0/1 -> RoPE+fp16 (Q/K), z=2 -> fp16 (V).
// ---------------------------------------------------------------------------
#define BK      32
#define ASTRIDE 80                    // 64B data + 16B pad per row
#define TILEB   (128 * ASTRIDE)       // 10240
#define OFF_A   0
#define OFF_B   TILEB
#define STAGEB  (2 * TILEB)           // 20480
#define GSMEM   67584                 // max(3*STAGEB=61440, rope staging 128*132*4)

template <int EPI>
__global__ __launch_bounds__(512, 2) void gemm_mma(
    const __half* __restrict__ A,
    const __half* __restrict__ B0, const __half* __restrict__ B1,
    const __half* __restrict__ B2,
    float* __restrict__ C,
    __half* __restrict__ O0, __half* __restrict__ O1, __half* __restrict__ O2,
    const float* __restrict__ cosT, const float* __restrict__ sinT) {
    extern __shared__ char smem[];
    const uint32_t sb = smem_u32(smem);
    const int tid = threadIdx.x;
    const int m0 = blockIdx.y * 128, n0 = blockIdx.x * 128;
    const int lane = tid & 31, wid = tid >> 5;
    const int wm = wid >> 2, wn = wid & 3;
    const int z = (EPI == 2) ? blockIdx.z : 0;

    const __half* B = (z == 0) ? B0 : (z == 1) ? B1 : B2;

    const int lrow = tid >> 2;          // 0..127
    const int lc16 = tid & 3;           // 0..3 (16B chunks per 64B row)
    const uint32_t sofs = lrow * ASTRIDE + lc16 * 16;

    const __half* a_base = A + (size_t)(m0 + lrow) * HID + lc16 * 8;
    const __half* b_base = B + (size_t)(n0 + lrow) * HID + lc16 * 8;

    float acc[2][4][4];
#pragma unroll
    for (int t = 0; t < 2; t++)
#pragma unroll
        for (int nt = 0; nt < 4; nt++)
#pragma unroll
            for (int e = 0; e < 4; e++) acc[t][nt][e] = 0.f;

    const uint32_t a_ld = sb + (uint32_t)((wm * 32 + (lane & 15)) * ASTRIDE + (lane >> 4) * 16);
    const uint32_t b_ld = sb + (uint32_t)((wn * 32 + ((lane >> 4) & 1) * 8 + (lane & 7)) * ASTRIDE
                                          + ((lane >> 3) & 1) * 16);

    const int NKT = HID / BK;   // 64

    // Prologue: stages 0, 1
#pragma unroll
    for (int p = 0; p < 2; p++) {
        uint32_t d = sb + p * STAGEB + sofs;
        size_t ge = (size_t)p * BK;
        CPA16(d + OFF_A, a_base + ge);
        CPA16(d + OFF_B, b_base + ge);
        CPA_COMMIT();
    }

    uint32_t st = 0, ld = 2 * STAGEB;
    for (int kt = 0; kt < NKT; kt++) {
        CPA_WAIT1();
        __syncthreads();   // stage st ready; all warps done computing slot ld

        if (kt + 2 < NKT) {
            uint32_t d = sb + ld + sofs;
            size_t ge = (size_t)(kt + 2) * BK;
            CPA16(d + OFF_A, a_base + ge);
            CPA16(d + OFF_B, b_base + ge);
        }
        CPA_COMMIT();

#pragma unroll
        for (int ksub = 0; ksub < 2; ksub++) {
            const uint32_t ko = ksub * 32;
            uint32_t ah[2][4];
#pragma unroll
            for (int t = 0; t < 2; t++)
                ldsm4(ah[t], a_ld + st + OFF_A + t * (16 * ASTRIDE) + ko);
#pragma unroll
            for (int p = 0; p < 2; p++) {
                uint32_t bh[4];
                ldsm4(bh, b_ld + st + OFF_B + p * (16 * ASTRIDE) + ko);
#pragma unroll
                for (int t = 0; t < 2; t++)
#pragma unroll
                    for (int hf = 0; hf < 2; hf++)
                        mma_f16(acc[t][p * 2 + hf], ah[t], &bh[hf * 2]);
            }
        }
        st += STAGEB; if (st == 3 * STAGEB) st = 0;
        ld += STAGEB; if (ld == 3 * STAGEB) ld = 0;
    }

    if (EPI == 0) {
#pragma unroll
        for (int t = 0; t < 2; t++) {
            int row = m0 + wm * 32 + t * 16 + (lane >> 2);
#pragma unroll
            for (int nt = 0; nt < 4; nt++) {
                int col = n0 + wn * 32 + nt * 8 + (lane & 3) * 2;
                *(float2*)&C[(size_t)row * HID + col] =
                    make_float2(acc[t][nt][0], acc[t][nt][1]);
                *(float2*)&C[(size_t)(row + 8) * HID + col] =
                    make_float2(acc[t][nt][2], acc[t][nt][3]);
            }
        }
    } else if (z == 2) {
        // V projection: fp16 store from registers
#pragma unroll
        for (int t = 0; t < 2; t++) {
            int row = m0 + wm * 32 + t * 16 + (lane >> 2);
#pragma unroll
            for (int nt = 0; nt < 4; nt++) {
                int col = n0 + wn * 32 + nt * 8 + (lane & 3) * 2;
                *(uint32_t*)&O2[(size_t)row * HID + col]       = pack_h2(acc[t][nt][0], acc[t][nt][1]);
                *(uint32_t*)&O2[(size_t)(row + 8) * HID + col] = pack_h2(acc[t][nt][2], acc[t][nt][3]);
            }
        }
    } else {
        // Q/K projection: RoPE + fp16 via smem staging
        __half* O = z ? O1 : O0;
        float* smf = (float*)smem;     // [128][132] fp32
        CPA_WAIT0();
        __syncthreads();               // all pending async copies drained; smem reusable
#pragma unroll
        for (int t = 0; t < 2; t++) {
            int r = wm * 32 + t * 16 + (lane >> 2);
            int c = wn * 32 + (lane & 3) * 2;
#pragma unroll
            for (int nt = 0; nt < 4; nt++) {
                int cc = c + nt * 8;
                smf[r * 132 + cc]       = acc[t][nt][0];
                smf[r * 132 + cc + 1]   = acc[t][nt][1];
                smf[(r + 8) * 132 + cc]     = acc[t][nt][2];
                smf[(r + 8) * 132 + cc + 1] = acc[t][nt][3];
            }
        }
        __syncthreads();
#pragma unroll
        for (int it = 0; it < 8; it++) {
            int p = it * 512 + tid;        // [0, 4096)
            int row = p >> 5;
            int i2 = (p & 31) * 2;
            float2 x1 = *(float2*)&smf[row * 132 + i2];
            float2 x2 = *(float2*)&smf[row * 132 + 64 + i2];
            int grow = m0 + row;
            int s = grow & (SEQ - 1);
            float2 cs = *(const float2*)&cosT[s * 64 + i2];
            float2 sn = *(const float2*)&sinT[s * 64 + i2];
            float r1a = x1.x * cs.x - x2.x * sn.x;
            float r1b = x1.y * cs.y - x2.y * sn.y;
            float r2a = x2.x * cs.x + x1.x * sn.x;
            float r2b = x2.y * cs.y + x1.y * sn.y;
            size_t o1 = (size_t)grow * HID + n0 + i2;
            *(uint32_t*)&O[o1]      = pack_h2(r1a, r1b);
            *(uint32_t*)&O[o1 + 64] = pack_h2(r2a, r2b);
        }
    }
}

// ---------------------------------------------------------------------------
// fp16 tensor-core flash attention (causal).
// CTA: 128 threads (4 warps), 64 q-rows; warp = m16 x n64. K tile = 64 keys.
// ---------------------------------------------------------------------------
#define AST    272                   // bytes per smem row (128 fp16 + 16 pad)
#define ATILE  (64 * AST)            // 17408
#define A_Q    0
#define A_K    (1 * ATILE)
#define A_V    (2 * ATILE)
#define ASMEM  (3 * ATILE)           // 52224

__global__ __launch_bounds__(128) void attn_tc(
    const __half* __restrict__ q, const __half* __restrict__ k,
    const __half* __restrict__ v, __half* __restrict__ ao) {
    extern __shared__ char smc[];
    const uint32_t sb = smem_u32(smc);
    const int tid = threadIdx.x, lane = tid & 31, wid = tid >> 5;
    const int qt = gridDim.x - 1 - blockIdx.x;     // heavy tiles first
    const int bh = blockIdx.y;
    const int b = bh >> 4, h = bh & 15;
    const size_t hoff = (size_t)b * SEQ * HID + (size_t)h * HDIM;

    // Q tile -> smem
    {
        const size_t qbase = hoff + (size_t)(qt * 64) * HID;
#pragma unroll
        for (int i = 0; i < 8; i++) {
            int idx = i * 128 + tid, row = idx >> 4, c16 = idx & 15;
            uint32_t so = row * AST + c16 * 16;
            CPA16(sb + A_Q + so, q + qbase + (size_t)row * HID + c16 * 8);
        }
        CPA_COMMIT();
    }

    float o[16][4];
#pragma unroll
    for (int nt = 0; nt < 16; nt++)
#pragma unroll
        for (int e = 0; e < 4; e++) o[nt][e] = 0.f;
    float m0 = -1e30f, m1 = -1e30f, l0 = 0.f, l1 = 0.f;
    const float scale = 0.08838834764831845f;

    const uint32_t a_q = sb + (uint32_t)((wid * 16 + (lane & 15)) * AST + (lane >> 4) * 16);
    const uint32_t b_k = sb + (uint32_t)((((lane & 7) + ((lane >> 4) & 1) * 8)) * AST + ((lane >> 3) & 1) * 16);
    const uint32_t b_v = sb + (uint32_t)((((lane & 7) + ((lane >> 3) & 1) * 8)) * AST + ((lane >> 4) & 1) * 16);

    const int grow0 = qt * 64 + wid * 16 + (lane >> 2);

    for (int j = 0; j <= qt; j++) {
        __syncthreads();
        {
            const size_t kbase = hoff + (size_t)(j * 64) * HID;
#pragma unroll
            for (int i = 0; i < 8; i++) {
                int idx = i * 128 + tid, row = idx >> 4, c16 = idx & 15;
                uint32_t so = row * AST + c16 * 16;
                size_t go = kbase + (size_t)row * HID + c16 * 8;
                CPA16(sb + A_K + so, k + go);
                CPA16(sb + A_V + so, v + go);
            }
            CPA_COMMIT();
        }
        CPA_WAIT0();
        __syncthreads();

        // S = Q K^T
        float s[8][4];
#pragma unroll
        for (int nt = 0; nt < 8; nt++)
#pragma unroll
            for (int e = 0; e < 4; e++) s[nt][e] = 0.f;

#pragma unroll
        for (int ks = 0; ks < 8; ks++) {
            uint32_t aQ[4];
            ldsm4(aQ, a_q + A_Q + ks * 32);
#pragma unroll
            for (int g = 0; g < 4; g++) {
                uint32_t bK[4];
                ldsm4(bK, b_k + A_K + g * (16 * AST) + ks * 32);
                mma_f16(s[2 * g],     aQ, bK);
                mma_f16(s[2 * g + 1], aQ, bK + 2);
            }
        }

        // Online softmax
        const bool diag = (j == qt);
        float mx0 = -1e30f, mx1 = -1e30f;
#pragma unroll
        for (int nt = 0; nt < 8; nt++) {
            int c0 = j * 64 + nt * 8 + (lane & 3) * 2;
#pragma unroll
            for (int e = 0; e < 4; e++) {
                float val = s[nt][e] * scale;
                if (diag && (c0 + (e & 1)) > (grow0 + (e >> 1) * 8)) val = -1e30f;
                s[nt][e] = val;
            }
            mx0 = fmaxf(mx0, fmaxf(s[nt][0], s[nt][1]));
            mx1 = fmaxf(mx1, fmaxf(s[nt][2], s[nt][3]));
        }
        mx0 = fmaxf(mx0, __shfl_xor_sync(0xffffffffu, mx0, 1));
        mx0 = fmaxf(mx0, __shfl_xor_sync(0xffffffffu, mx0, 2));
        mx1 = fmaxf(mx1, __shfl_xor_sync(0xffffffffu, mx1, 1));
        mx1 = fmaxf(mx1, __shfl_xor_sync(0xffffffffu, mx1, 2));
        float mn0 = fmaxf(m0, mx0), mn1 = fmaxf(m1, mx1);
        float cr0 = __expf(m0 - mn0), cr1 = __expf(m1 - mn1);
        m0 = mn0; m1 = mn1;
        float sum0 = 0.f, sum1 = 0.f;
#pragma unroll
        for (int nt = 0; nt < 8; nt++) {
            s[nt][0] = __expf(s[nt][0] - mn0);
            s[nt][1] = __expf(s[nt][1] - mn0);
            s[nt][2] = __expf(s[nt][2] - mn1);
            s[nt][3] = __expf(s[nt][3] - mn1);
            sum0 += s[nt][0] + s[nt][1];
            sum1 += s[nt][2] + s[nt][3];
        }
        sum0 += __shfl_xor_sync(0xffffffffu, sum0, 1);
        sum0 += __shfl_xor_sync(0xffffffffu, sum0, 2);
        sum1 += __shfl_xor_sync(0xffffffffu, sum1, 1);
        sum1 += __shfl_xor_sync(0xffffffffu, sum1, 2);
        l0 = l0 * cr0 + sum0;
        l1 = l1 * cr1 + sum1;
#pragma unroll
        for (int nt = 0; nt < 16; nt++) {
            o[nt][0] *= cr0; o[nt][1] *= cr0;
            o[nt][2] *= cr1; o[nt][3] *= cr1;
        }

        // O += P V  (P packed to fp16 A-frags in registers; V via ldmatrix.trans)
#pragma unroll
        for (int kc = 0; kc < 4; kc++) {
            uint32_t pH[4];
            pH[0] = pack_h2(s[2 * kc][0],     s[2 * kc][1]);
            pH[1] = pack_h2(s[2 * kc][2],     s[2 * kc][3]);
            pH[2] = pack_h2(s[2 * kc + 1][0], s[2 * kc + 1][1]);
            pH[3] = pack_h2(s[2 * kc + 1][2], s[2 * kc + 1][3]);

            uint32_t vbase = b_v + A_V + kc * (16 * AST);
#pragma unroll
            for (int ng = 0; ng < 8; ng++) {
                uint32_t vH[4];
                ldsm4t(vH, vbase + ng * 32);
                mma_f16(o[2 * ng],     pH, vH);
                mma_f16(o[2 * ng + 1], pH, vH + 2);
            }
        }
    }

    // Epilogue: normalize, fp16 store
    float inv0 = 1.f / l0, inv1 = 1.f / l1;
    int row0 = b * SEQ + qt * 64 + wid * 16 + (lane >> 2);
#pragma unroll
    for (int nt = 0; nt < 16; nt++) {
        int col = h * HDIM + nt * 8 + (lane & 3) * 2;
        *(uint32_t*)&ao[(size_t)row0 * HID + col] =
            pack_h2(o[nt][0] * inv0, o[nt][1] * inv0);
        *(uint32_t*)&ao[(size_t)(row0 + 8) * HID + col] =
            pack_h2(o[nt][2] * inv1, o[nt][3] * inv1);
    }
}

// ---------------------------------------------------------------------------
// Launch
// ---------------------------------------------------------------------------
extern "C" void kernel_launch(void* const* d_in, const int* in_sizes, int n_in,
                              void* d_out, int out_size) {
    const float* hs = (const float*)d_in[0];
    const float* Wq = (const float*)d_in[1];
    const float* Wk = (const float*)d_in[2];
    const float* Wv = (const float*)d_in[3];
    const float* Wo = (const float*)d_in[4];
    float* out = (float*)d_out;

    float *cosT, *sinT;
    cudaGetSymbolAddress((void**)&cosT, g_cosT);
    cudaGetSymbolAddress((void**)&sinT, g_sinT);

    __half *hsp, *aop, *wp, *qp, *kp, *vp;
    cudaGetSymbolAddress((void**)&hsp, g_hs);
    cudaGetSymbolAddress((void**)&aop, g_ao);
    cudaGetSymbolAddress((void**)&wp,  g_w);
    cudaGetSymbolAddress((void**)&qp,  g_q);
    cudaGetSymbolAddress((void**)&kp,  g_k);
    cudaGetSymbolAddress((void**)&vp,  g_v);

    const size_t WN = (size_t)HID * HID;
    const int n4_hs = MTOT * HID / 4;
    const int n4_w  = (int)(WN / 4);

    cvt_kernel<<<(n4_hs + 255) / 256, 256>>>(hs, hsp, n4_hs);
    cvt_w4<<<dim3((n4_w + 255) / 256, 4), 256>>>(Wq, Wk, Wv, Wo, wp, n4_w);
    rope_table<<<(SEQ * 64) / 256, 256>>>(cosT, sinT);

    cudaFuncSetAttribute(gemm_mma<0>, cudaFuncAttributeMaxDynamicSharedMemorySize, GSMEM);
    cudaFuncSetAttribute(gemm_mma<2>, cudaFuncAttributeMaxDynamicSharedMemorySize, GSMEM);

    dim3 gg(HID / 128, MTOT / 128);          // (16, 32)
    dim3 gg3(HID / 128, MTOT / 128, 3);      // Q, K, V in one launch

    // QKV projections: z=0 -> Q (RoPE), z=1 -> K (RoPE), z=2 -> V
    gemm_mma<2><<<gg3, 512, GSMEM>>>(hsp,
                                     wp + 0 * WN, wp + 1 * WN, wp + 2 * WN,
                                     nullptr,
                                     qp, kp, vp, cosT, sinT);

    cudaFuncSetAttribute(attn_tc, cudaFuncAttributeMaxDynamicSharedMemorySize, ASMEM);
    attn_tc<<<dim3(SEQ / 64, BATCH * NHEADS), 128, ASMEM>>>(qp, kp, vp, aop);

    // Output projection, fp32 store
    gemm_mma<0><<<gg, 512, GSMEM>>>(aop,
                                    wp + 3 * WN, nullptr, nullptr,
                                    out,
                                    nullptr, nullptr, nullptr,
                                    nullptr, nullptr);
}